// round 12
// baseline (speedup 1.0000x reference)
#include <cuda_runtime.h>
#include <cuda_bf16.h>
#include <math.h>
#include <stdint.h>

// ---------------- problem constants ----------------
#define QLEN   1024
#define BSZ    2
#define DMODEL 1024
#define NHEAD  16
#define DHEAD  64
#define NLAYER 4
#define MLEN_  1024
#define KLEN_  2048
#define QKV3   (3*DMODEL)

// ---------------- scratch (device globals; no allocation) ----------------
__device__ float g_pos_emb[KLEN_*DMODEL];                       // tf32-rounded
__device__ float g_catL[(size_t)NLAYER*KLEN_*BSZ*DMODEL];       // 64 MB, tf32-rounded
__device__ float g_wheads[KLEN_*BSZ*QKV3];                      // tf32-rounded
__device__ float g_rhk[(size_t)NLAYER*KLEN_*DMODEL];            // tf32-rounded
__device__ float g_attnvec[QLEN*BSZ*DMODEL];                    // tf32-rounded
__device__ float g_tmp[QLEN*BSZ*DMODEL];                        // fp32
__device__ float g_ff1[QLEN*BSZ*DMODEL];                        // tf32-rounded
__device__ float g_core[QLEN*BSZ*DMODEL];                       // fp32
__device__ float g_core_r[QLEN*BSZ*DMODEL];                     // tf32-rounded
// rounded weight copies
__device__ float g_wr_qkv[(size_t)NLAYER*DMODEL*QKV3];
__device__ float g_wr_rw [(size_t)NLAYER*DMODEL*DMODEL];
__device__ float g_wr_ow [(size_t)NLAYER*DMODEL*DMODEL];
__device__ float g_wr_f1 [(size_t)NLAYER*DMODEL*DMODEL];
__device__ float g_wr_f2 [(size_t)NLAYER*DMODEL*DMODEL];

// ---------------- helpers ----------------
__device__ __forceinline__ uint32_t f2tf(float f) {
    uint32_t r;
    asm("cvt.rna.tf32.f32 %0, %1;" : "=r"(r) : "f"(f));
    return r;
}

__device__ __forceinline__ void mma_tf32(float* c,
    uint32_t a0, uint32_t a1, uint32_t a2, uint32_t a3,
    uint32_t b0, uint32_t b1)
{
    asm volatile(
        "mma.sync.aligned.m16n8k8.row.col.f32.tf32.tf32.f32 "
        "{%0,%1,%2,%3}, {%4,%5,%6,%7}, {%8,%9}, {%0,%1,%2,%3};\n"
        : "+f"(c[0]), "+f"(c[1]), "+f"(c[2]), "+f"(c[3])
        : "r"(a0), "r"(a1), "r"(a2), "r"(a3), "r"(b0), "r"(b1));
}

__device__ __forceinline__ void cpasync16(uint32_t dst, const float* src) {
    asm volatile("cp.async.ca.shared.global [%0], [%1], 16;" :: "r"(dst), "l"(src));
}
__device__ __forceinline__ uint32_t smem_u32(const void* p) {
    return (uint32_t)__cvta_generic_to_shared(p);
}

// ---------------- tf32 rounding (grid-stride, float4, z-batched) ----------
__global__ void round_tf32_kernel(const float* __restrict__ src,
                                  float* __restrict__ dst, int n4,
                                  long long s4, long long d4)
{
    const float4* sp = ((const float4*)src) + (long long)blockIdx.z * s4;
    float4* dp = ((float4*)dst) + (long long)blockIdx.z * d4;
    int i = blockIdx.x * blockDim.x + threadIdx.x;
    int stride = gridDim.x * blockDim.x;
    for (; i < n4; i += stride) {
        float4 v = sp[i];
        uint4 r = make_uint4(f2tf(v.x), f2tf(v.y), f2tf(v.z), f2tf(v.w));
        dp[i] = *(float4*)&r;
    }
}

// ---------------- positional embedding (tf32-rounded) ----------------
__global__ void pos_emb_kernel() {
    int p = blockIdx.x;
    float pos = (float)(KLEN_ - 1 - p);
    for (int f = threadIdx.x; f < DMODEL/2; f += blockDim.x) {
        double e = -((double)(2*f) / (double)DMODEL) * log(10000.0);
        float invf = (float)exp(e);
        float arg = pos * invf;
        g_pos_emb[p*DMODEL + f]            = __uint_as_float(f2tf(sinf(arg)));
        g_pos_emb[p*DMODEL + DMODEL/2 + f] = __uint_as_float(f2tf(cosf(arg)));
    }
}

// ---------------- TF32 GEMM: 256 threads, 128x64 tile, 3-stage cp.async ----
// 8 warps in 4(m)x2(n) grid, warp tile 32x32. 44.5KB smem -> 2 blocks/SM.
#define GSTAGES 3
template<bool RELU, bool HASBIAS, bool ROUNDC>
__global__ void __launch_bounds__(256) gemm_tc(
    const float* __restrict__ A, int lda, long long aSz,
    const float* __restrict__ B, int ldb, long long bSz,
    float* __restrict__ C, int ldc, long long cSz,
    const float* __restrict__ bias, int K)
{
    __shared__ uint32_t As[GSTAGES][128][20];
    __shared__ uint32_t Bs[GSTAGES][16][72];

    const int tid  = threadIdx.x;
    const int lane = tid & 31;
    const int wid  = tid >> 5;           // 0..7
    const int wm   = (wid >> 1) * 32;    // 0,32,64,96
    const int wn   = (wid & 1) * 32;     // 0,32
    const int br   = blockIdx.y, bc = blockIdx.x, bz = blockIdx.z;
    const int lg   = lane >> 2;
    const int lk   = lane & 3;

    A += (long long)bz * aSz;
    B += (long long)bz * bSz;
    C += (long long)bz * cSz;

    float acc[2][4][4];
    #pragma unroll
    for (int i = 0; i < 2; i++)
        #pragma unroll
        for (int j = 0; j < 4; j++)
            #pragma unroll
            for (int r = 0; r < 4; r++) acc[i][j][r] = 0.f;

    const int arow = tid >> 1;            // 0..127
    const int acol = (tid & 1) * 8;       // 0 or 8
    const int brow = tid >> 4;            // 0..15
    const int bcol = (tid & 15) * 4;      // 0..60

    const float* Ap = A + (size_t)(br*128 + arow) * lda + acol;
    const float* Bp = B + (size_t)brow * ldb + bc*64 + bcol;

    const int nIter = K >> 4;

    #pragma unroll
    for (int s = 0; s < GSTAGES-1; s++) {
        if (s < nIter) {
            cpasync16(smem_u32(&As[s][arow][acol]),   Ap + s*16);
            cpasync16(smem_u32(&As[s][arow][acol+4]), Ap + s*16 + 4);
            cpasync16(smem_u32(&Bs[s][brow][bcol]),   Bp + (size_t)s*16 * ldb);
        }
        asm volatile("cp.async.commit_group;");
    }

    int buf = 0, pf = GSTAGES-1;
    for (int it = 0; it < nIter; it++) {
        asm volatile("cp.async.wait_group %0;" :: "n"(GSTAGES-2));
        __syncthreads();

        if (it + GSTAGES-1 < nIter) {
            const int s = pf;
            const float* ap = Ap + (it + GSTAGES-1)*16;
            const float* bp = Bp + (size_t)(it + GSTAGES-1)*16 * ldb;
            cpasync16(smem_u32(&As[s][arow][acol]),   ap);
            cpasync16(smem_u32(&As[s][arow][acol+4]), ap + 4);
            cpasync16(smem_u32(&Bs[s][brow][bcol]),   bp);
        }
        asm volatile("cp.async.commit_group;");

        #pragma unroll
        for (int s = 0; s < 2; s++) {
            const int k0 = s*8 + lk;
            uint32_t bf[4][2];
            #pragma unroll
            for (int nt = 0; nt < 4; nt++) {
                int n = wn + nt*8 + lg;
                bf[nt][0] = Bs[buf][k0][n];
                bf[nt][1] = Bs[buf][k0+4][n];
            }
            #pragma unroll
            for (int mt = 0; mt < 2; mt++) {
                int m = wm + mt*16 + lg;
                uint32_t a0 = As[buf][m][k0];
                uint32_t a1 = As[buf][m+8][k0];
                uint32_t a2 = As[buf][m][k0+4];
                uint32_t a3 = As[buf][m+8][k0+4];
                #pragma unroll
                for (int nt = 0; nt < 4; nt++)
                    mma_tf32(acc[mt][nt], a0, a1, a2, a3, bf[nt][0], bf[nt][1]);
            }
        }
        buf = (buf == GSTAGES-1) ? 0 : buf+1;
        pf  = (pf  == GSTAGES-1) ? 0 : pf+1;
    }

    #pragma unroll
    for (int mt = 0; mt < 2; mt++) {
        int r0 = br*128 + wm + mt*16 + lg;
        #pragma unroll
        for (int nt = 0; nt < 4; nt++) {
            int c0 = bc*64 + wn + nt*8 + lk*2;
            float v0 = acc[mt][nt][0], v1 = acc[mt][nt][1];
            float v2 = acc[mt][nt][2], v3 = acc[mt][nt][3];
            if (HASBIAS) {
                float b0v = bias[c0], b1v = bias[c0+1];
                v0 += b0v; v1 += b1v; v2 += b0v; v3 += b1v;
            }
            if (RELU) {
                v0 = fmaxf(v0, 0.f); v1 = fmaxf(v1, 0.f);
                v2 = fmaxf(v2, 0.f); v3 = fmaxf(v3, 0.f);
            }
            if (ROUNDC) {
                v0 = __uint_as_float(f2tf(v0)); v1 = __uint_as_float(f2tf(v1));
                v2 = __uint_as_float(f2tf(v2)); v3 = __uint_as_float(f2tf(v3));
            }
            *(float2*)(C + (size_t)r0 * ldc + c0)     = make_float2(v0, v1);
            *(float2*)(C + (size_t)(r0+8) * ldc + c0) = make_float2(v2, v3);
        }
    }
}

// ---------------- fused flash attention (Q in regs, circular rhk band) -----
#define RSLOTS 320
#define FLASH_SMEM_WORDS (4352*2 + RSLOTS*68 + 8448*2)
#define FLASH_SMEM_BYTES (FLASH_SMEM_WORDS * 4)

__global__ void __launch_bounds__(256) flash_attn(
    const float* __restrict__ rwb, const float* __restrict__ rrb,
    const float* __restrict__ rhk)
{
    extern __shared__ uint32_t sm[];
    uint32_t* Ks = sm;                 // [64][68]
    uint32_t* Vs = sm + 4352;          // [64][68]
    uint32_t* Rs = sm + 8704;          // [RSLOTS][68] circular by global row
    uint32_t* BD = sm + 8704 + RSLOTS*68;  // [2][64][132]

    const int tid  = threadIdx.x;
    const int lane = tid & 31;
    const int w    = tid >> 5;
    const int lg   = lane >> 2, lk = lane & 3;
    const int half = w >> 2;
    const int wl   = w & 3;
    const int i0   = (7 - (int)blockIdx.x) * 128;
    const int i0h  = i0 + half * 64;
    const int z    = blockIdx.y;
    const int bb   = z >> 4, n = z & 15;

    uint32_t* BDh = BD + half * 8448;
    const int rloc = wl*16 + lg;

    uint32_t qwf[8][4], qrf[8][4];
    {
        const float* qb_w = rwb + n*DHEAD;
        const float* qb_r = rrb + n*DHEAD;
        const float* q0 = g_wheads + ((size_t)(MLEN_ + i0h + rloc)     * BSZ + bb) * QKV3 + n*DHEAD;
        const float* q1 = g_wheads + ((size_t)(MLEN_ + i0h + rloc + 8) * BSZ + bb) * QKV3 + n*DHEAD;
        #pragma unroll
        for (int s = 0; s < 8; s++) {
            int k0 = s*8 + lk;
            float v00 = q0[k0],   v10 = q1[k0];
            float v01 = q0[k0+4], v11 = q1[k0+4];
            float bw0 = qb_w[k0], bw1 = qb_w[k0+4];
            float br0 = qb_r[k0], br1 = qb_r[k0+4];
            qwf[s][0] = f2tf(v00+bw0); qwf[s][1] = f2tf(v10+bw0);
            qwf[s][2] = f2tf(v01+bw1); qwf[s][3] = f2tf(v11+bw1);
            qrf[s][0] = f2tf(v00+br0); qrf[s][1] = f2tf(v10+br0);
            qrf[s][2] = f2tf(v01+br1); qrf[s][3] = f2tf(v11+br1);
        }
    }

    float accO[8][4];
    #pragma unroll
    for (int a = 0; a < 8; a++)
        #pragma unroll
        for (int r = 0; r < 4; r++) accO[a][r] = 0.f;
    float m0 = -1e30f, m1 = -1e30f, l0 = 0.f, l1 = 0.f;

    const int ntiles = 18 + (i0 >> 6);
    const int bm0 = 896 - i0;

    #pragma unroll
    for (int p = 0; p < 16; p++) {
        int f = tid + 256*p;
        int r = f >> 4, c4 = (f & 15) * 4;
        int ug = bm0 + r;
        int slot = ug % RSLOTS;
        int rr = ug > KLEN_-1 ? KLEN_-1 : ug;
        cpasync16(smem_u32(&Rs[slot*68 + c4]), rhk + (size_t)rr * DMODEL + n*DHEAD + c4);
    }
    asm volatile("cp.async.commit_group;");

    for (int jt = 0; jt < ntiles; jt++) {
        const int j0 = jt * 64;
        const int bm = bm0 + j0;
        asm volatile("cp.async.wait_group 0;");
        __syncthreads();

        {
            uint4 kv[4], vv[4];
            #pragma unroll
            for (int p = 0; p < 4; p++) {
                int f = tid + 256*p;
                int r = f >> 4, c4 = (f & 15) * 4;
                const float* kp = g_wheads + ((size_t)(j0 + r) * BSZ + bb) * QKV3
                                  + DMODEL + n*DHEAD + c4;
                kv[p] = *(const uint4*)kp;
                vv[p] = *(const uint4*)(kp + DMODEL);
            }
            #pragma unroll
            for (int p = 0; p < 4; p++) {
                int f = tid + 256*p;
                int r = f >> 4, c4 = (f & 15) * 4;
                *(uint4*)&Ks[r*68 + c4] = kv[p];
                *(uint4*)&Vs[r*68 + c4] = vv[p];
            }
        }
        __syncthreads();

        if (jt + 1 < ntiles) {
            #pragma unroll
            for (int p = 0; p < 4; p++) {
                int f = tid + 256*p;
                int r = f >> 4, c4 = (f & 15) * 4;
                int ug = bm + 256 + r;
                int slot = ug % RSLOTS;
                int rr = ug > KLEN_-1 ? KLEN_-1 : ug;
                cpasync16(smem_u32(&Rs[slot*68 + c4]), rhk + (size_t)rr * DMODEL + n*DHEAD + c4);
            }
        }
        asm volatile("cp.async.commit_group;");

        if (j0 <= MLEN_ + i0h + 63) {
            float accS[8][4];
            #pragma unroll
            for (int a = 0; a < 8; a++)
                #pragma unroll
                for (int r = 0; r < 4; r++) accS[a][r] = 0.f;
            #pragma unroll
            for (int s = 0; s < 8; s++) {
                int k0 = s*8 + lk;
                #pragma unroll
                for (int nt = 0; nt < 8; nt++) {
                    int j = nt*8 + lg;
                    mma_tf32(accS[nt], qwf[s][0], qwf[s][1], qwf[s][2], qwf[s][3],
                             Ks[j*68+k0], Ks[j*68+k0+4]);
                }
            }
            #pragma unroll
            for (int hc = 0; hc < 2; hc++) {
                float accB[8][4];
                #pragma unroll
                for (int a = 0; a < 8; a++)
                    #pragma unroll
                    for (int r = 0; r < 4; r++) accB[a][r] = 0.f;
                int rowb[8];
                #pragma unroll
                for (int nt = 0; nt < 8; nt++)
                    rowb[nt] = (bm + (1-half)*64 + hc*64 + nt*8) % RSLOTS;
                #pragma unroll
                for (int s = 0; s < 8; s++) {
                    int k0 = s*8 + lk;
                    #pragma unroll
                    for (int nt = 0; nt < 8; nt++) {
                        int u = rowb[nt] + lg;
                        mma_tf32(accB[nt], qrf[s][0], qrf[s][1], qrf[s][2], qrf[s][3],
                                 Rs[u*68+k0], Rs[u*68+k0+4]);
                    }
                }
                #pragma unroll
                for (int nt = 0; nt < 8; nt++) {
                    int u = hc*64 + nt*8 + lk*2;
                    BDh[rloc*132 + u]        = __float_as_uint(accB[nt][0]);
                    BDh[rloc*132 + u + 1]    = __float_as_uint(accB[nt][1]);
                    BDh[(rloc+8)*132 + u]    = __float_as_uint(accB[nt][2]);
                    BDh[(rloc+8)*132 + u + 1]= __float_as_uint(accB[nt][3]);
                }
            }
            __syncwarp();
            float mx0 = -1e30f, mx1 = -1e30f;
            #pragma unroll
            for (int nt = 0; nt < 8; nt++) {
                #pragma unroll
                for (int q = 0; q < 2; q++) {
                    int jj = nt*8 + lk*2 + q;
                    float b0 = __uint_as_float(BDh[rloc*132 + jj - rloc + 63]);
                    float b1 = __uint_as_float(BDh[(rloc+8)*132 + jj - rloc + 55]);
                    float s0 = (accS[nt][q]   + b0) * 0.125f;
                    float s1 = (accS[nt][2+q] + b1) * 0.125f;
                    if (j0 + jj > MLEN_ + i0h + rloc)     s0 = -1e30f;
                    if (j0 + jj > MLEN_ + i0h + rloc + 8) s1 = -1e30f;
                    accS[nt][q]   = s0; mx0 = fmaxf(mx0, s0);
                    accS[nt][2+q] = s1; mx1 = fmaxf(mx1, s1);
                }
            }
            mx0 = fmaxf(mx0, __shfl_xor_sync(0xffffffffu, mx0, 1));
            mx0 = fmaxf(mx0, __shfl_xor_sync(0xffffffffu, mx0, 2));
            mx1 = fmaxf(mx1, __shfl_xor_sync(0xffffffffu, mx1, 1));
            mx1 = fmaxf(mx1, __shfl_xor_sync(0xffffffffu, mx1, 2));
            float mn0 = fmaxf(m0, mx0), mn1 = fmaxf(m1, mx1);
            float al0 = __expf(m0 - mn0), al1 = __expf(m1 - mn1);
            m0 = mn0; m1 = mn1;
            float rs0 = 0.f, rs1 = 0.f;
            #pragma unroll
            for (int nt = 0; nt < 8; nt++) {
                #pragma unroll
                for (int q = 0; q < 2; q++) {
                    float p0 = __expf(accS[nt][q]   - mn0);
                    float p1 = __expf(accS[nt][2+q] - mn1);
                    accS[nt][q] = p0;   rs0 += p0;
                    accS[nt][2+q] = p1; rs1 += p1;
                }
            }
            rs0 += __shfl_xor_sync(0xffffffffu, rs0, 1);
            rs0 += __shfl_xor_sync(0xffffffffu, rs0, 2);
            rs1 += __shfl_xor_sync(0xffffffffu, rs1, 1);
            rs1 += __shfl_xor_sync(0xffffffffu, rs1, 2);
            l0 = l0*al0 + rs0; l1 = l1*al1 + rs1;
            #pragma unroll
            for (int nt = 0; nt < 8; nt++) {
                accO[nt][0] *= al0; accO[nt][1] *= al0;
                accO[nt][2] *= al1; accO[nt][3] *= al1;
            }
            __syncwarp();
            #pragma unroll
            for (int nt = 0; nt < 8; nt++) {
                int c = nt*8 + lk*2;
                BDh[rloc*132 + c]       = f2tf(accS[nt][0]);
                BDh[rloc*132 + c + 1]   = f2tf(accS[nt][1]);
                BDh[(rloc+8)*132 + c]   = f2tf(accS[nt][2]);
                BDh[(rloc+8)*132 + c+1] = f2tf(accS[nt][3]);
            }
            __syncwarp();
            #pragma unroll
            for (int s = 0; s < 8; s++) {
                int k0 = s*8 + lk;
                uint32_t a0 = BDh[rloc*132 + k0];
                uint32_t a1 = BDh[(rloc+8)*132 + k0];
                uint32_t a2 = BDh[rloc*132 + k0 + 4];
                uint32_t a3 = BDh[(rloc+8)*132 + k0 + 4];
                #pragma unroll
                for (int nt = 0; nt < 8; nt++) {
                    int d = nt*8 + lg;
                    mma_tf32(accO[nt], a0, a1, a2, a3, Vs[k0*68+d], Vs[(k0+4)*68+d]);
                }
            }
        }
    }

    float inv0 = 1.f / l0, inv1 = 1.f / l1;
    #pragma unroll
    for (int nt = 0; nt < 8; nt++) {
        int d = n*DHEAD + nt*8 + lk*2;
        int ig = i0h + rloc;
        float2 o0 = make_float2(__uint_as_float(f2tf(accO[nt][0]*inv0)),
                                __uint_as_float(f2tf(accO[nt][1]*inv0)));
        float2 o1 = make_float2(__uint_as_float(f2tf(accO[nt][2]*inv1)),
                                __uint_as_float(f2tf(accO[nt][3]*inv1)));
        *(float2*)(g_attnvec + ((size_t)ig * BSZ + bb) * DMODEL + d)     = o0;
        *(float2*)(g_attnvec + ((size_t)(ig+8) * BSZ + bb) * DMODEL + d) = o1;
    }
}

// ---------------- residual add + layernorm, fused extra outputs ------------
// writes g_core (fp32) always; rdst (tf32-rounded copy) and e1 (fp32 copy) optional.
__global__ void __launch_bounds__(256) add_ln_kernel(
    const float* __restrict__ x, const float* __restrict__ g, const float* __restrict__ b,
    float* __restrict__ rdst, float* __restrict__ e1)
{
    int r = blockIdx.x;
    int tid = threadIdx.x;
    size_t base = (size_t)r * DMODEL + tid * 4;
    float4 c4 = *(const float4*)(g_core + base);
    float4 x4 = *(const float4*)(x + base);
    float v0 = c4.x + x4.x, v1 = c4.y + x4.y, v2 = c4.z + x4.z, v3 = c4.w + x4.w;

    __shared__ float red1[8];
    __shared__ float red2[8];

    float s = v0 + v1 + v2 + v3;
    #pragma unroll
    for (int o = 16; o > 0; o >>= 1) s += __shfl_xor_sync(0xffffffffu, s, o);
    if ((tid & 31) == 0) red1[tid >> 5] = s;
    __syncthreads();
    float tot = red1[0];
    #pragma unroll
    for (int w = 1; w < 8; w++) tot += red1[w];
    float mean = tot * (1.f / DMODEL);

    float d0 = v0 - mean, d1 = v1 - mean, d2 = v2 - mean, d3 = v3 - mean;
    float sq = d0*d0 + d1*d1 + d2*d2 + d3*d3;
    #pragma unroll
    for (int o = 16; o > 0; o >>= 1) sq += __shfl_xor_sync(0xffffffffu, sq, o);
    if ((tid & 31) == 0) red2[tid >> 5] = sq;
    __syncthreads();
    float tot2 = red2[0];
    #pragma unroll
    for (int w = 1; w < 8; w++) tot2 += red2[w];
    float var = tot2 * (1.f / DMODEL);
    float inv = rsqrtf(var + 1e-5f);

    float4 g4 = *(const float4*)(g + tid*4);
    float4 b4 = *(const float4*)(b + tid*4);
    float4 o4;
    o4.x = d0 * inv * g4.x + b4.x;
    o4.y = d1 * inv * g4.y + b4.y;
    o4.z = d2 * inv * g4.z + b4.z;
    o4.w = d3 * inv * g4.w + b4.w;
    *(float4*)(g_core + base) = o4;
    if (e1) *(float4*)(e1 + base) = o4;
    if (rdst) {
        uint4 r4 = make_uint4(f2tf(o4.x), f2tf(o4.y), f2tf(o4.z), f2tf(o4.w));
        *(float4*)(rdst + base) = *(float4*)&r4;
    }
}

// ---------------- launch ----------------
extern "C" void kernel_launch(void* const* d_in, const int* in_sizes, int n_in,
                              void* d_out, int out_size)
{
    const float* mems = (const float*)d_in[0];
    const float* raw  = (const float*)d_in[1];
    const float* rwb  = (const float*)d_in[3];
    const float* rrb  = (const float*)d_in[4];
    const float* qkvw = (const float*)d_in[5];
    const float* rw   = (const float*)d_in[6];
    const float* ow   = (const float*)d_in[7];
    const float* ln1g = (const float*)d_in[8];
    const float* ln1b = (const float*)d_in[9];
    const float* ffw1 = (const float*)d_in[10];
    const float* ffb1 = (const float*)d_in[11];
    const float* ffw2 = (const float*)d_in[12];
    const float* ffb2 = (const float*)d_in[13];
    const float* ln2g = (const float*)d_in[14];
    const float* ln2b = (const float*)d_in[15];

    float *p_pos, *p_catL, *p_wheads, *p_rhk, *p_attnvec, *p_tmp, *p_ff1, *p_core, *p_core_r;
    float *p_wqkv, *p_wrw, *p_wow, *p_wf1, *p_wf2;
    cudaGetSymbolAddress((void**)&p_pos, g_pos_emb);
    cudaGetSymbolAddress((void**)&p_catL, g_catL);
    cudaGetSymbolAddress((void**)&p_wheads, g_wheads);
    cudaGetSymbolAddress((void**)&p_rhk, g_rhk);
    cudaGetSymbolAddress((void**)&p_attnvec, g_attnvec);
    cudaGetSymbolAddress((void**)&p_tmp, g_tmp);
    cudaGetSymbolAddress((void**)&p_ff1, g_ff1);
    cudaGetSymbolAddress((void**)&p_core, g_core);
    cudaGetSymbolAddress((void**)&p_core_r, g_core_r);
    cudaGetSymbolAddress((void**)&p_wqkv, g_wr_qkv);
    cudaGetSymbolAddress((void**)&p_wrw, g_wr_rw);
    cudaGetSymbolAddress((void**)&p_wow, g_wr_ow);
    cudaGetSymbolAddress((void**)&p_wf1, g_wr_f1);
    cudaGetSymbolAddress((void**)&p_wf2, g_wr_f2);

    cudaFuncSetAttribute(flash_attn, cudaFuncAttributeMaxDynamicSharedMemorySize,
                         FLASH_SMEM_BYTES);

    const size_t CORE_N = (size_t)QLEN * BSZ * DMODEL;
    const size_t CAT_N  = 2 * CORE_N;
    const size_t MEMS_N = (size_t)(NLAYER + 1) * CORE_N;
    const size_t CORE_BYTES = CORE_N * sizeof(float);
    const size_t RHK_N = (size_t)KLEN_ * DMODEL;
    const size_t WSQ = (size_t)NLAYER * DMODEL * DMODEL;

    float* out_core = nullptr;
    float* out_mems = nullptr;
    if ((size_t)out_size == CORE_N + MEMS_N) {
        out_core = (float*)d_out;
        out_mems = (float*)d_out + CORE_N;
    } else if ((size_t)out_size == MEMS_N) {
        out_mems = (float*)d_out;
    } else {
        out_core = (float*)d_out;
    }

    pos_emb_kernel<<<KLEN_, 256>>>();
    cudaMemcpyAsync(p_core, raw, CORE_BYTES, cudaMemcpyDeviceToDevice);
    if (out_mems)
        cudaMemcpyAsync(out_mems, raw, CORE_BYTES, cudaMemcpyDeviceToDevice);

    // pre-round weights (once per launch)
    round_tf32_kernel<<<2048, 256>>>(qkvw, p_wqkv, (int)((size_t)NLAYER*DMODEL*QKV3/4), 0, 0);
    round_tf32_kernel<<<2048, 256>>>(rw,   p_wrw,  (int)(WSQ/4), 0, 0);
    round_tf32_kernel<<<2048, 256>>>(ow,   p_wow,  (int)(WSQ/4), 0, 0);
    round_tf32_kernel<<<2048, 256>>>(ffw1, p_wf1,  (int)(WSQ/4), 0, 0);
    round_tf32_kernel<<<2048, 256>>>(ffw2, p_wf2,  (int)(WSQ/4), 0, 0);

    // pre-round mems into every layer's cat first half (z-batched)
    round_tf32_kernel<<<dim3(512,1,NLAYER), 256>>>(
        mems, p_catL, (int)(CORE_N/4), (long long)(CORE_N/4), (long long)(CAT_N/4));
    // layer-0 core half = round(raw)
    round_tf32_kernel<<<512, 256>>>(raw, p_catL + CORE_N, (int)(CORE_N/4), 0, 0);

    // rhk for ALL layers (batched over z), output rounded
    gemm_tc<false,false,true><<<dim3(DMODEL/64, KLEN_/128, NLAYER), 256>>>(
        p_pos, DMODEL, 0LL,
        p_wrw, DMODEL, (long long)DMODEL*DMODEL,
        p_rhk, DMODEL, (long long)RHK_N,
        nullptr, DMODEL);

    for (int l = 0; l < NLAYER; l++) {
        const float* qkvw_l = p_wqkv + (size_t)l * DMODEL * QKV3;
        const float* cat_l  = p_catL + (size_t)l * CAT_N;

        // K,V for all 4096 rows (rounded out)
        gemm_tc<false,false,true><<<dim3(2048/64, (KLEN_*BSZ)/128), 256>>>(
            cat_l, DMODEL, 0LL, qkvw_l + DMODEL, QKV3, 0LL,
            p_wheads + DMODEL, QKV3, 0LL, nullptr, DMODEL);

        // Q only for last 2048 rows (rounded out)
        gemm_tc<false,false,true><<<dim3(DMODEL/64, (QLEN*BSZ)/128), 256>>>(
            cat_l + (size_t)2048*DMODEL, DMODEL, 0LL, qkvw_l, QKV3, 0LL,
            p_wheads + (size_t)2048*QKV3, QKV3, 0LL, nullptr, DMODEL);

        // fused attention (writes rounded attnvec)
        flash_attn<<<dim3(QLEN/128, BSZ*NHEAD), 256, FLASH_SMEM_BYTES>>>(
            rwb, rrb, p_rhk + (size_t)l * RHK_N);

        // attn_out = attn_vec @ o_w[l]  (fp32 out)
        gemm_tc<false,false,false><<<dim3(DMODEL/64, (QLEN*BSZ)/128), 256>>>(
            p_attnvec, DMODEL, 0LL, p_wow + (size_t)l * DMODEL * DMODEL, DMODEL, 0LL,
            p_tmp, DMODEL, 0LL, nullptr, DMODEL);

        // core = LN(core + attn_out); rounded copy for ff1
        add_ln_kernel<<<QLEN*BSZ, 256>>>(p_tmp, ln1g + l*DMODEL, ln1b + l*DMODEL,
                                         p_core_r, nullptr);

        // ff1 = relu(core @ w1 + b1), rounded out
        gemm_tc<true,true,true><<<dim3(DMODEL/64, (QLEN*BSZ)/128), 256>>>(
            p_core_r, DMODEL, 0LL, p_wf1 + (size_t)l * DMODEL * DMODEL, DMODEL, 0LL,
            p_ff1, DMODEL, 0LL, ffb1 + l*DMODEL, DMODEL);

        // ff2 (fp32 out)
        gemm_tc<false,true,false><<<dim3(DMODEL/64, (QLEN*BSZ)/128), 256>>>(
            p_ff1, DMODEL, 0LL, p_wf2 + (size_t)l * DMODEL * DMODEL, DMODEL, 0LL,
            p_tmp, DMODEL, 0LL, ffb2 + l*DMODEL, DMODEL);

        // core = LN(core + ff); rounded directly into next layer's cat; fp32 into out_mems
        float* rdst = (l + 1 < NLAYER) ? p_catL + (size_t)(l+1) * CAT_N + CORE_N : nullptr;
        float* e1   = out_mems ? out_mems + (size_t)(l+1) * CORE_N : nullptr;
        add_ln_kernel<<<QLEN*BSZ, 256>>>(p_tmp, ln2g + l*DMODEL, ln2b + l*DMODEL,
                                         rdst, e1);
    }

    if (out_core)
        cudaMemcpyAsync(out_core, p_core, CORE_BYTES, cudaMemcpyDeviceToDevice);
}

// round 13
// speedup vs baseline: 1.1486x; 1.1486x over previous
#include <cuda_runtime.h>
#include <cuda_bf16.h>
#include <math.h>
#include <stdint.h>

// ---------------- problem constants ----------------
#define QLEN   1024
#define BSZ    2
#define DMODEL 1024
#define NHEAD  16
#define DHEAD  64
#define NLAYER 4
#define MLEN_  1024
#define KLEN_  2048
#define QKV3   (3*DMODEL)

// ---------------- scratch (device globals; no allocation) ----------------
__device__ float g_pos_emb[KLEN_*DMODEL];                       // tf32-rounded
__device__ float g_catL[(size_t)NLAYER*KLEN_*BSZ*DMODEL];       // 64 MB, tf32-rounded
__device__ float g_wheads[KLEN_*BSZ*QKV3];                      // tf32-rounded
__device__ float g_rhk[(size_t)NLAYER*KLEN_*DMODEL];            // tf32-rounded
__device__ float g_attnvec[QLEN*BSZ*DMODEL];                    // tf32-rounded
__device__ float g_tmp[QLEN*BSZ*DMODEL];                        // fp32
__device__ float g_ff1[QLEN*BSZ*DMODEL];                        // tf32-rounded
__device__ float g_core[QLEN*BSZ*DMODEL];                       // fp32
__device__ float g_core_r[QLEN*BSZ*DMODEL];                     // tf32-rounded
// rounded weight copies
__device__ float g_wr_qkv[(size_t)NLAYER*DMODEL*QKV3];
__device__ float g_wr_rw [(size_t)NLAYER*DMODEL*DMODEL];
__device__ float g_wr_ow [(size_t)NLAYER*DMODEL*DMODEL];
__device__ float g_wr_f1 [(size_t)NLAYER*DMODEL*DMODEL];
__device__ float g_wr_f2 [(size_t)NLAYER*DMODEL*DMODEL];

// ---------------- helpers ----------------
__device__ __forceinline__ uint32_t f2tf(float f) {
    uint32_t r;
    asm("cvt.rna.tf32.f32 %0, %1;" : "=r"(r) : "f"(f));
    return r;
}

__device__ __forceinline__ void mma_tf32(float* c,
    uint32_t a0, uint32_t a1, uint32_t a2, uint32_t a3,
    uint32_t b0, uint32_t b1)
{
    asm volatile(
        "mma.sync.aligned.m16n8k8.row.col.f32.tf32.tf32.f32 "
        "{%0,%1,%2,%3}, {%4,%5,%6,%7}, {%8,%9}, {%0,%1,%2,%3};\n"
        : "+f"(c[0]), "+f"(c[1]), "+f"(c[2]), "+f"(c[3])
        : "r"(a0), "r"(a1), "r"(a2), "r"(a3), "r"(b0), "r"(b1));
}

__device__ __forceinline__ void cpasync16(uint32_t dst, const float* src) {
    asm volatile("cp.async.ca.shared.global [%0], [%1], 16;" :: "r"(dst), "l"(src));
}
__device__ __forceinline__ uint32_t smem_u32(const void* p) {
    return (uint32_t)__cvta_generic_to_shared(p);
}

// ---------------- tf32 rounding (grid-stride, float4, z-batched) ----------
__global__ void round_tf32_kernel(const float* __restrict__ src,
                                  float* __restrict__ dst, int n4,
                                  long long s4, long long d4)
{
    const float4* sp = ((const float4*)src) + (long long)blockIdx.z * s4;
    float4* dp = ((float4*)dst) + (long long)blockIdx.z * d4;
    int i = blockIdx.x * blockDim.x + threadIdx.x;
    int stride = gridDim.x * blockDim.x;
    for (; i < n4; i += stride) {
        float4 v = sp[i];
        uint4 r = make_uint4(f2tf(v.x), f2tf(v.y), f2tf(v.z), f2tf(v.w));
        dp[i] = *(float4*)&r;
    }
}

// ---------------- positional embedding (tf32-rounded) ----------------
__global__ void pos_emb_kernel() {
    int p = blockIdx.x;
    float pos = (float)(KLEN_ - 1 - p);
    for (int f = threadIdx.x; f < DMODEL/2; f += blockDim.x) {
        double e = -((double)(2*f) / (double)DMODEL) * log(10000.0);
        float invf = (float)exp(e);
        float arg = pos * invf;
        g_pos_emb[p*DMODEL + f]            = __uint_as_float(f2tf(sinf(arg)));
        g_pos_emb[p*DMODEL + DMODEL/2 + f] = __uint_as_float(f2tf(cosf(arg)));
    }
}

// ---------------- TF32 GEMM: 512 threads, 128x128 tile, 4-stage (R11) ------
#define STAGES 4
template<bool RELU, bool HASBIAS, bool ROUNDC>
__global__ void __launch_bounds__(512) gemm_tc(
    const float* __restrict__ A, int lda, long long aSz,
    const float* __restrict__ B, int ldb, long long bSz,
    float* __restrict__ C, int ldc, long long cSz,
    const float* __restrict__ bias, int K)
{
    __shared__ uint32_t As[STAGES][128][20];
    __shared__ uint32_t Bs[STAGES][16][136];

    const int tid  = threadIdx.x;
    const int lane = tid & 31;
    const int wid  = tid >> 5;
    const int wm   = (wid >> 2) * 32;
    const int wn   = (wid & 3) * 32;
    const int br   = blockIdx.y, bc = blockIdx.x, bz = blockIdx.z;
    const int lg   = lane >> 2;
    const int lk   = lane & 3;

    A += (long long)bz * aSz;
    B += (long long)bz * bSz;
    C += (long long)bz * cSz;

    float acc[2][4][4];
    #pragma unroll
    for (int i = 0; i < 2; i++)
        #pragma unroll
        for (int j = 0; j < 4; j++)
            #pragma unroll
            for (int r = 0; r < 4; r++) acc[i][j][r] = 0.f;

    const int arow = tid >> 2;
    const int acol = (tid & 3) * 4;
    const int brow = tid >> 5;
    const int bcol = (tid & 31) * 4;

    const float* Ap = A + (size_t)(br*128 + arow) * lda + acol;
    const float* Bp = B + (size_t)brow * ldb + bc*128 + bcol;

    const int nIter = K >> 4;

    #pragma unroll
    for (int s = 0; s < STAGES-1; s++) {
        if (s < nIter) {
            cpasync16(smem_u32(&As[s][arow][acol]), Ap + s*16);
            cpasync16(smem_u32(&Bs[s][brow][bcol]), Bp + (size_t)s*16 * ldb);
        }
        asm volatile("cp.async.commit_group;");
    }

    for (int it = 0; it < nIter; it++) {
        asm volatile("cp.async.wait_group %0;" :: "n"(STAGES-2));
        __syncthreads();

        if (it + STAGES-1 < nIter) {
            const int s = (it + STAGES-1) & (STAGES-1);
            cpasync16(smem_u32(&As[s][arow][acol]), Ap + (it + STAGES-1)*16);
            cpasync16(smem_u32(&Bs[s][brow][bcol]), Bp + (size_t)(it + STAGES-1)*16 * ldb);
        }
        asm volatile("cp.async.commit_group;");

        const int buf = it & (STAGES-1);
        #pragma unroll
        for (int s = 0; s < 2; s++) {
            const int k0 = s*8 + lk;
            uint32_t bf[4][2];
            #pragma unroll
            for (int nt = 0; nt < 4; nt++) {
                int n = wn + nt*8 + lg;
                bf[nt][0] = Bs[buf][k0][n];
                bf[nt][1] = Bs[buf][k0+4][n];
            }
            #pragma unroll
            for (int mt = 0; mt < 2; mt++) {
                int m = wm + mt*16 + lg;
                uint32_t a0 = As[buf][m][k0];
                uint32_t a1 = As[buf][m+8][k0];
                uint32_t a2 = As[buf][m][k0+4];
                uint32_t a3 = As[buf][m+8][k0+4];
                #pragma unroll
                for (int nt = 0; nt < 4; nt++)
                    mma_tf32(acc[mt][nt], a0, a1, a2, a3, bf[nt][0], bf[nt][1]);
            }
        }
    }

    #pragma unroll
    for (int mt = 0; mt < 2; mt++) {
        int r0 = br*128 + wm + mt*16 + lg;
        #pragma unroll
        for (int nt = 0; nt < 4; nt++) {
            int c0 = bc*128 + wn + nt*8 + lk*2;
            float v0 = acc[mt][nt][0], v1 = acc[mt][nt][1];
            float v2 = acc[mt][nt][2], v3 = acc[mt][nt][3];
            if (HASBIAS) {
                float b0v = bias[c0], b1v = bias[c0+1];
                v0 += b0v; v1 += b1v; v2 += b0v; v3 += b1v;
            }
            if (RELU) {
                v0 = fmaxf(v0, 0.f); v1 = fmaxf(v1, 0.f);
                v2 = fmaxf(v2, 0.f); v3 = fmaxf(v3, 0.f);
            }
            if (ROUNDC) {
                v0 = __uint_as_float(f2tf(v0)); v1 = __uint_as_float(f2tf(v1));
                v2 = __uint_as_float(f2tf(v2)); v3 = __uint_as_float(f2tf(v3));
            }
            *(float2*)(C + (size_t)r0 * ldc + c0)     = make_float2(v0, v1);
            *(float2*)(C + (size_t)(r0+8) * ldc + c0) = make_float2(v2, v3);
        }
    }
}

// ---------------- fused flash attention (Q in regs, circular rhk band) -----
#define RSLOTS 320
#define FLASH_SMEM_WORDS (4352*2 + RSLOTS*68 + 8448*2)
#define FLASH_SMEM_BYTES (FLASH_SMEM_WORDS * 4)

__global__ void __launch_bounds__(256) flash_attn(
    const float* __restrict__ rwb, const float* __restrict__ rrb,
    const float* __restrict__ rhk)
{
    extern __shared__ uint32_t sm[];
    uint32_t* Ks = sm;                 // [64][68]
    uint32_t* Vs = sm + 4352;          // [64][68]
    uint32_t* Rs = sm + 8704;          // [RSLOTS][68] circular by global row
    uint32_t* BD = sm + 8704 + RSLOTS*68;  // [2][64][132]

    const int tid  = threadIdx.x;
    const int lane = tid & 31;
    const int w    = tid >> 5;
    const int lg   = lane >> 2, lk = lane & 3;
    const int half = w >> 2;
    const int wl   = w & 3;
    const int i0   = (7 - (int)blockIdx.x) * 128;
    const int i0h  = i0 + half * 64;
    const int z    = blockIdx.y;
    const int bb   = z >> 4, n = z & 15;

    uint32_t* BDh = BD + half * 8448;
    const int rloc = wl*16 + lg;

    uint32_t qwf[8][4], qrf[8][4];
    {
        const float* qb_w = rwb + n*DHEAD;
        const float* qb_r = rrb + n*DHEAD;
        const float* q0 = g_wheads + ((size_t)(MLEN_ + i0h + rloc)     * BSZ + bb) * QKV3 + n*DHEAD;
        const float* q1 = g_wheads + ((size_t)(MLEN_ + i0h + rloc + 8) * BSZ + bb) * QKV3 + n*DHEAD;
        #pragma unroll
        for (int s = 0; s < 8; s++) {
            int k0 = s*8 + lk;
            float v00 = q0[k0],   v10 = q1[k0];
            float v01 = q0[k0+4], v11 = q1[k0+4];
            float bw0 = qb_w[k0], bw1 = qb_w[k0+4];
            float br0 = qb_r[k0], br1 = qb_r[k0+4];
            qwf[s][0] = f2tf(v00+bw0); qwf[s][1] = f2tf(v10+bw0);
            qwf[s][2] = f2tf(v01+bw1); qwf[s][3] = f2tf(v11+bw1);
            qrf[s][0] = f2tf(v00+br0); qrf[s][1] = f2tf(v10+br0);
            qrf[s][2] = f2tf(v01+br1); qrf[s][3] = f2tf(v11+br1);
        }
    }

    float accO[8][4];
    #pragma unroll
    for (int a = 0; a < 8; a++)
        #pragma unroll
        for (int r = 0; r < 4; r++) accO[a][r] = 0.f;
    float m0 = -1e30f, m1 = -1e30f, l0 = 0.f, l1 = 0.f;

    const int ntiles = 18 + (i0 >> 6);
    const int bm0 = 896 - i0;

    #pragma unroll
    for (int p = 0; p < 16; p++) {
        int f = tid + 256*p;
        int r = f >> 4, c4 = (f & 15) * 4;
        int ug = bm0 + r;
        int slot = ug % RSLOTS;
        int rr = ug > KLEN_-1 ? KLEN_-1 : ug;
        cpasync16(smem_u32(&Rs[slot*68 + c4]), rhk + (size_t)rr * DMODEL + n*DHEAD + c4);
    }
    asm volatile("cp.async.commit_group;");

    for (int jt = 0; jt < ntiles; jt++) {
        const int j0 = jt * 64;
        const int bm = bm0 + j0;
        asm volatile("cp.async.wait_group 0;");
        __syncthreads();

        {
            uint4 kv[4], vv[4];
            #pragma unroll
            for (int p = 0; p < 4; p++) {
                int f = tid + 256*p;
                int r = f >> 4, c4 = (f & 15) * 4;
                const float* kp = g_wheads + ((size_t)(j0 + r) * BSZ + bb) * QKV3
                                  + DMODEL + n*DHEAD + c4;
                kv[p] = *(const uint4*)kp;
                vv[p] = *(const uint4*)(kp + DMODEL);
            }
            #pragma unroll
            for (int p = 0; p < 4; p++) {
                int f = tid + 256*p;
                int r = f >> 4, c4 = (f & 15) * 4;
                *(uint4*)&Ks[r*68 + c4] = kv[p];
                *(uint4*)&Vs[r*68 + c4] = vv[p];
            }
        }
        __syncthreads();

        if (jt + 1 < ntiles) {
            #pragma unroll
            for (int p = 0; p < 4; p++) {
                int f = tid + 256*p;
                int r = f >> 4, c4 = (f & 15) * 4;
                int ug = bm + 256 + r;
                int slot = ug % RSLOTS;
                int rr = ug > KLEN_-1 ? KLEN_-1 : ug;
                cpasync16(smem_u32(&Rs[slot*68 + c4]), rhk + (size_t)rr * DMODEL + n*DHEAD + c4);
            }
        }
        asm volatile("cp.async.commit_group;");

        if (j0 <= MLEN_ + i0h + 63) {
            float accS[8][4];
            #pragma unroll
            for (int a = 0; a < 8; a++)
                #pragma unroll
                for (int r = 0; r < 4; r++) accS[a][r] = 0.f;
            #pragma unroll
            for (int s = 0; s < 8; s++) {
                int k0 = s*8 + lk;
                #pragma unroll
                for (int nt = 0; nt < 8; nt++) {
                    int j = nt*8 + lg;
                    mma_tf32(accS[nt], qwf[s][0], qwf[s][1], qwf[s][2], qwf[s][3],
                             Ks[j*68+k0], Ks[j*68+k0+4]);
                }
            }
            #pragma unroll
            for (int hc = 0; hc < 2; hc++) {
                float accB[8][4];
                #pragma unroll
                for (int a = 0; a < 8; a++)
                    #pragma unroll
                    for (int r = 0; r < 4; r++) accB[a][r] = 0.f;
                int rowb[8];
                #pragma unroll
                for (int nt = 0; nt < 8; nt++)
                    rowb[nt] = (bm + (1-half)*64 + hc*64 + nt*8) % RSLOTS;
                #pragma unroll
                for (int s = 0; s < 8; s++) {
                    int k0 = s*8 + lk;
                    #pragma unroll
                    for (int nt = 0; nt < 8; nt++) {
                        int u = rowb[nt] + lg;
                        mma_tf32(accB[nt], qrf[s][0], qrf[s][1], qrf[s][2], qrf[s][3],
                                 Rs[u*68+k0], Rs[u*68+k0+4]);
                    }
                }
                #pragma unroll
                for (int nt = 0; nt < 8; nt++) {
                    int u = hc*64 + nt*8 + lk*2;
                    BDh[rloc*132 + u]        = __float_as_uint(accB[nt][0]);
                    BDh[rloc*132 + u + 1]    = __float_as_uint(accB[nt][1]);
                    BDh[(rloc+8)*132 + u]    = __float_as_uint(accB[nt][2]);
                    BDh[(rloc+8)*132 + u + 1]= __float_as_uint(accB[nt][3]);
                }
            }
            __syncwarp();
            float mx0 = -1e30f, mx1 = -1e30f;
            #pragma unroll
            for (int nt = 0; nt < 8; nt++) {
                #pragma unroll
                for (int q = 0; q < 2; q++) {
                    int jj = nt*8 + lk*2 + q;
                    float b0 = __uint_as_float(BDh[rloc*132 + jj - rloc + 63]);
                    float b1 = __uint_as_float(BDh[(rloc+8)*132 + jj - rloc + 55]);
                    float s0 = (accS[nt][q]   + b0) * 0.125f;
                    float s1 = (accS[nt][2+q] + b1) * 0.125f;
                    if (j0 + jj > MLEN_ + i0h + rloc)     s0 = -1e30f;
                    if (j0 + jj > MLEN_ + i0h + rloc + 8) s1 = -1e30f;
                    accS[nt][q]   = s0; mx0 = fmaxf(mx0, s0);
                    accS[nt][2+q] = s1; mx1 = fmaxf(mx1, s1);
                }
            }
            mx0 = fmaxf(mx0, __shfl_xor_sync(0xffffffffu, mx0, 1));
            mx0 = fmaxf(mx0, __shfl_xor_sync(0xffffffffu, mx0, 2));
            mx1 = fmaxf(mx1, __shfl_xor_sync(0xffffffffu, mx1, 1));
            mx1 = fmaxf(mx1, __shfl_xor_sync(0xffffffffu, mx1, 2));
            float mn0 = fmaxf(m0, mx0), mn1 = fmaxf(m1, mx1);
            float al0 = __expf(m0 - mn0), al1 = __expf(m1 - mn1);
            m0 = mn0; m1 = mn1;
            float rs0 = 0.f, rs1 = 0.f;
            #pragma unroll
            for (int nt = 0; nt < 8; nt++) {
                #pragma unroll
                for (int q = 0; q < 2; q++) {
                    float p0 = __expf(accS[nt][q]   - mn0);
                    float p1 = __expf(accS[nt][2+q] - mn1);
                    accS[nt][q] = p0;   rs0 += p0;
                    accS[nt][2+q] = p1; rs1 += p1;
                }
            }
            rs0 += __shfl_xor_sync(0xffffffffu, rs0, 1);
            rs0 += __shfl_xor_sync(0xffffffffu, rs0, 2);
            rs1 += __shfl_xor_sync(0xffffffffu, rs1, 1);
            rs1 += __shfl_xor_sync(0xffffffffu, rs1, 2);
            l0 = l0*al0 + rs0; l1 = l1*al1 + rs1;
            #pragma unroll
            for (int nt = 0; nt < 8; nt++) {
                accO[nt][0] *= al0; accO[nt][1] *= al0;
                accO[nt][2] *= al1; accO[nt][3] *= al1;
            }
            __syncwarp();
            #pragma unroll
            for (int nt = 0; nt < 8; nt++) {
                int c = nt*8 + lk*2;
                BDh[rloc*132 + c]       = f2tf(accS[nt][0]);
                BDh[rloc*132 + c + 1]   = f2tf(accS[nt][1]);
                BDh[(rloc+8)*132 + c]   = f2tf(accS[nt][2]);
                BDh[(rloc+8)*132 + c+1] = f2tf(accS[nt][3]);
            }
            __syncwarp();
            #pragma unroll
            for (int s = 0; s < 8; s++) {
                int k0 = s*8 + lk;
                uint32_t a0 = BDh[rloc*132 + k0];
                uint32_t a1 = BDh[(rloc+8)*132 + k0];
                uint32_t a2 = BDh[rloc*132 + k0 + 4];
                uint32_t a3 = BDh[(rloc+8)*132 + k0 + 4];
                #pragma unroll
                for (int nt = 0; nt < 8; nt++) {
                    int d = nt*8 + lg;
                    mma_tf32(accO[nt], a0, a1, a2, a3, Vs[k0*68+d], Vs[(k0+4)*68+d]);
                }
            }
        }
    }

    float inv0 = 1.f / l0, inv1 = 1.f / l1;
    #pragma unroll
    for (int nt = 0; nt < 8; nt++) {
        int d = n*DHEAD + nt*8 + lk*2;
        int ig = i0h + rloc;
        float2 o0 = make_float2(__uint_as_float(f2tf(accO[nt][0]*inv0)),
                                __uint_as_float(f2tf(accO[nt][1]*inv0)));
        float2 o1 = make_float2(__uint_as_float(f2tf(accO[nt][2]*inv1)),
                                __uint_as_float(f2tf(accO[nt][3]*inv1)));
        *(float2*)(g_attnvec + ((size_t)ig * BSZ + bb) * DMODEL + d)     = o0;
        *(float2*)(g_attnvec + ((size_t)(ig+8) * BSZ + bb) * DMODEL + d) = o1;
    }
}

// ---------------- residual add + layernorm, fused extra outputs ------------
__global__ void __launch_bounds__(256) add_ln_kernel(
    const float* __restrict__ x, const float* __restrict__ g, const float* __restrict__ b,
    float* __restrict__ rdst, float* __restrict__ e1)
{
    int r = blockIdx.x;
    int tid = threadIdx.x;
    size_t base = (size_t)r * DMODEL + tid * 4;
    float4 c4 = *(const float4*)(g_core + base);
    float4 x4 = *(const float4*)(x + base);
    float v0 = c4.x + x4.x, v1 = c4.y + x4.y, v2 = c4.z + x4.z, v3 = c4.w + x4.w;

    __shared__ float red1[8];
    __shared__ float red2[8];

    float s = v0 + v1 + v2 + v3;
    #pragma unroll
    for (int o = 16; o > 0; o >>= 1) s += __shfl_xor_sync(0xffffffffu, s, o);
    if ((tid & 31) == 0) red1[tid >> 5] = s;
    __syncthreads();
    float tot = red1[0];
    #pragma unroll
    for (int w = 1; w < 8; w++) tot += red1[w];
    float mean = tot * (1.f / DMODEL);

    float d0 = v0 - mean, d1 = v1 - mean, d2 = v2 - mean, d3 = v3 - mean;
    float sq = d0*d0 + d1*d1 + d2*d2 + d3*d3;
    #pragma unroll
    for (int o = 16; o > 0; o >>= 1) sq += __shfl_xor_sync(0xffffffffu, sq, o);
    if ((tid & 31) == 0) red2[tid >> 5] = sq;
    __syncthreads();
    float tot2 = red2[0];
    #pragma unroll
    for (int w = 1; w < 8; w++) tot2 += red2[w];
    float var = tot2 * (1.f / DMODEL);
    float inv = rsqrtf(var + 1e-5f);

    float4 g4 = *(const float4*)(g + tid*4);
    float4 b4 = *(const float4*)(b + tid*4);
    float4 o4;
    o4.x = d0 * inv * g4.x + b4.x;
    o4.y = d1 * inv * g4.y + b4.y;
    o4.z = d2 * inv * g4.z + b4.z;
    o4.w = d3 * inv * g4.w + b4.w;
    *(float4*)(g_core + base) = o4;
    if (e1) *(float4*)(e1 + base) = o4;
    if (rdst) {
        uint4 r4 = make_uint4(f2tf(o4.x), f2tf(o4.y), f2tf(o4.z), f2tf(o4.w));
        *(float4*)(rdst + base) = *(float4*)&r4;
    }
}

// ---------------- launch ----------------
extern "C" void kernel_launch(void* const* d_in, const int* in_sizes, int n_in,
                              void* d_out, int out_size)
{
    const float* mems = (const float*)d_in[0];
    const float* raw  = (const float*)d_in[1];
    const float* rwb  = (const float*)d_in[3];
    const float* rrb  = (const float*)d_in[4];
    const float* qkvw = (const float*)d_in[5];
    const float* rw   = (const float*)d_in[6];
    const float* ow   = (const float*)d_in[7];
    const float* ln1g = (const float*)d_in[8];
    const float* ln1b = (const float*)d_in[9];
    const float* ffw1 = (const float*)d_in[10];
    const float* ffb1 = (const float*)d_in[11];
    const float* ffw2 = (const float*)d_in[12];
    const float* ffb2 = (const float*)d_in[13];
    const float* ln2g = (const float*)d_in[14];
    const float* ln2b = (const float*)d_in[15];

    float *p_pos, *p_catL, *p_wheads, *p_rhk, *p_attnvec, *p_tmp, *p_ff1, *p_core, *p_core_r;
    float *p_wqkv, *p_wrw, *p_wow, *p_wf1, *p_wf2;
    cudaGetSymbolAddress((void**)&p_pos, g_pos_emb);
    cudaGetSymbolAddress((void**)&p_catL, g_catL);
    cudaGetSymbolAddress((void**)&p_wheads, g_wheads);
    cudaGetSymbolAddress((void**)&p_rhk, g_rhk);
    cudaGetSymbolAddress((void**)&p_attnvec, g_attnvec);
    cudaGetSymbolAddress((void**)&p_tmp, g_tmp);
    cudaGetSymbolAddress((void**)&p_ff1, g_ff1);
    cudaGetSymbolAddress((void**)&p_core, g_core);
    cudaGetSymbolAddress((void**)&p_core_r, g_core_r);
    cudaGetSymbolAddress((void**)&p_wqkv, g_wr_qkv);
    cudaGetSymbolAddress((void**)&p_wrw, g_wr_rw);
    cudaGetSymbolAddress((void**)&p_wow, g_wr_ow);
    cudaGetSymbolAddress((void**)&p_wf1, g_wr_f1);
    cudaGetSymbolAddress((void**)&p_wf2, g_wr_f2);

    cudaFuncSetAttribute(flash_attn, cudaFuncAttributeMaxDynamicSharedMemorySize,
                         FLASH_SMEM_BYTES);

    const size_t CORE_N = (size_t)QLEN * BSZ * DMODEL;
    const size_t CAT_N  = 2 * CORE_N;
    const size_t MEMS_N = (size_t)(NLAYER + 1) * CORE_N;
    const size_t CORE_BYTES = CORE_N * sizeof(float);
    const size_t RHK_N = (size_t)KLEN_ * DMODEL;
    const size_t WSQ = (size_t)NLAYER * DMODEL * DMODEL;

    float* out_core = nullptr;
    float* out_mems = nullptr;
    if ((size_t)out_size == CORE_N + MEMS_N) {
        out_core = (float*)d_out;
        out_mems = (float*)d_out + CORE_N;
    } else if ((size_t)out_size == MEMS_N) {
        out_mems = (float*)d_out;
    } else {
        out_core = (float*)d_out;
    }

    pos_emb_kernel<<<KLEN_, 256>>>();
    cudaMemcpyAsync(p_core, raw, CORE_BYTES, cudaMemcpyDeviceToDevice);
    if (out_mems)
        cudaMemcpyAsync(out_mems, raw, CORE_BYTES, cudaMemcpyDeviceToDevice);

    // pre-round weights (once per launch)
    round_tf32_kernel<<<2048, 256>>>(qkvw, p_wqkv, (int)((size_t)NLAYER*DMODEL*QKV3/4), 0, 0);
    round_tf32_kernel<<<2048, 256>>>(rw,   p_wrw,  (int)(WSQ/4), 0, 0);
    round_tf32_kernel<<<2048, 256>>>(ow,   p_wow,  (int)(WSQ/4), 0, 0);
    round_tf32_kernel<<<2048, 256>>>(ffw1, p_wf1,  (int)(WSQ/4), 0, 0);
    round_tf32_kernel<<<2048, 256>>>(ffw2, p_wf2,  (int)(WSQ/4), 0, 0);

    // pre-round mems into every layer's cat first half (z-batched)
    round_tf32_kernel<<<dim3(512,1,NLAYER), 256>>>(
        mems, p_catL, (int)(CORE_N/4), (long long)(CORE_N/4), (long long)(CAT_N/4));
    // layer-0 core half = round(raw)
    round_tf32_kernel<<<512, 256>>>(raw, p_catL + CORE_N, (int)(CORE_N/4), 0, 0);

    // rhk for ALL layers (batched over z), output rounded
    gemm_tc<false,false,true><<<dim3(DMODEL/128, KLEN_/128, NLAYER), 512>>>(
        p_pos, DMODEL, 0LL,
        p_wrw, DMODEL, (long long)DMODEL*DMODEL,
        p_rhk, DMODEL, (long long)RHK_N,
        nullptr, DMODEL);

    for (int l = 0; l < NLAYER; l++) {
        const float* qkvw_l = p_wqkv + (size_t)l * DMODEL * QKV3;
        const float* cat_l  = p_catL + (size_t)l * CAT_N;

        // K,V for all 4096 rows (rounded out)
        gemm_tc<false,false,true><<<dim3(2048/128, (KLEN_*BSZ)/128), 512>>>(
            cat_l, DMODEL, 0LL, qkvw_l + DMODEL, QKV3, 0LL,
            p_wheads + DMODEL, QKV3, 0LL, nullptr, DMODEL);

        // Q only for last 2048 rows (rounded out)
        gemm_tc<false,false,true><<<dim3(DMODEL/128, (QLEN*BSZ)/128), 512>>>(
            cat_l + (size_t)2048*DMODEL, DMODEL, 0LL, qkvw_l, QKV3, 0LL,
            p_wheads + (size_t)2048*QKV3, QKV3, 0LL, nullptr, DMODEL);

        // fused attention (writes rounded attnvec)
        flash_attn<<<dim3(QLEN/128, BSZ*NHEAD), 256, FLASH_SMEM_BYTES>>>(
            rwb, rrb, p_rhk + (size_t)l * RHK_N);

        // attn_out = attn_vec @ o_w[l]  (fp32 out)
        gemm_tc<false,false,false><<<dim3(DMODEL/128, (QLEN*BSZ)/128), 512>>>(
            p_attnvec, DMODEL, 0LL, p_wow + (size_t)l * DMODEL * DMODEL, DMODEL, 0LL,
            p_tmp, DMODEL, 0LL, nullptr, DMODEL);

        // core = LN(core + attn_out); rounded copy for ff1
        add_ln_kernel<<<QLEN*BSZ, 256>>>(p_tmp, ln1g + l*DMODEL, ln1b + l*DMODEL,
                                         p_core_r, nullptr);

        // ff1 = relu(core @ w1 + b1), rounded out
        gemm_tc<true,true,true><<<dim3(DMODEL/128, (QLEN*BSZ)/128), 512>>>(
            p_core_r, DMODEL, 0LL, p_wf1 + (size_t)l * DMODEL * DMODEL, DMODEL, 0LL,
            p_ff1, DMODEL, 0LL, ffb1 + l*DMODEL, DMODEL);

        // ff2 (fp32 out)
        gemm_tc<false,true,false><<<dim3(DMODEL/128, (QLEN*BSZ)/128), 512>>>(
            p_ff1, DMODEL, 0LL, p_wf2 + (size_t)l * DMODEL * DMODEL, DMODEL, 0LL,
            p_tmp, DMODEL, 0LL, ffb2 + l*DMODEL, DMODEL);

        // core = LN(core + ff); rounded into next layer's cat; fp32 into out_mems
        float* rdst = (l + 1 < NLAYER) ? p_catL + (size_t)(l+1) * CAT_N + CORE_N : nullptr;
        float* e1   = out_mems ? out_mems + (size_t)(l+1) * CORE_N : nullptr;
        add_ln_kernel<<<QLEN*BSZ, 256>>>(p_tmp, ln2g + l*DMODEL, ln2b + l*DMODEL,
                                         rdst, e1);
    }

    if (out_core)
        cudaMemcpyAsync(out_core, p_core, CORE_BYTES, cudaMemcpyDeviceToDevice);
}